// round 2
// baseline (speedup 1.0000x reference)
#include <cuda_runtime.h>

#define NN 100000
#define EE 600000
#define HH 128
#define GG 1000
#define BN_EPS 1e-5f

// ---- scratch (alloc-free: __device__ globals) ----
__device__ float g_t[NN * HH];     // x + agg (pre-MLP)
__device__ float g_u[NN * HH];     // after GEMM1+BN+ReLU
__device__ float g_h[NN * HH];     // layer output features
__device__ float g_t3[NN * 3];     // layer-0 pre-MLP (3 feats)
__device__ float g_pool[GG * HH];  // pooled per-graph

__device__ __forceinline__ float* buf(int id) {
    return id == 0 ? g_t : (id == 1 ? g_u : g_h);
}

// ---- layer 0: copy x into t3 ----
__global__ void k_copy3(const float* __restrict__ x) {
    int i = blockIdx.x * blockDim.x + threadIdx.x;
    if (i < NN * 3) g_t3[i] = x[i];
}

// ---- layer 0: scatter-add x[src] into t3[dst] (3 feats/edge) ----
__global__ void k_scatter3(const float* __restrict__ x, const int* __restrict__ ei) {
    int e = blockIdx.x * blockDim.x + threadIdx.x;
    if (e >= EE) return;
    int s = ei[e];
    int d = ei[EE + e];
#pragma unroll
    for (int f = 0; f < 3; f++) atomicAdd(&g_t3[d * 3 + f], x[s * 3 + f]);
}

// ---- layer 0: (N,3)@(3,128) + bias + BN + ReLU -> g_u ----
__global__ void k_mlp0(const float* __restrict__ W1, const float* __restrict__ b1,
                       const float* __restrict__ gam, const float* __restrict__ bet,
                       const float* __restrict__ mu, const float* __restrict__ var) {
    int idx = blockIdx.x * blockDim.x + threadIdx.x;
    if (idx >= NN * HH) return;
    int n = idx >> 7;
    int j = idx & 127;
    float h = g_t3[n * 3 + 0] * W1[j]
            + g_t3[n * 3 + 1] * W1[HH + j]
            + g_t3[n * 3 + 2] * W1[2 * HH + j]
            + b1[j];
    float sc = gam[j] * rsqrtf(var[j] + BN_EPS);
    h = (h - mu[j]) * sc + bet[j];
    g_u[idx] = fmaxf(h, 0.f);
}

// ---- copy g_h -> g_t (float4) ----
__global__ void k_copyh() {
    int i = blockIdx.x * blockDim.x + threadIdx.x;
    if (i < NN * HH / 4) ((float4*)g_t)[i] = ((const float4*)g_h)[i];
}

// ---- edge scatter: g_t[dst] += g_h[src], one thread per (edge, float4) ----
__global__ void k_scatter(const int* __restrict__ ei) {
    int idx = blockIdx.x * blockDim.x + threadIdx.x;
    if (idx >= EE * 32) return;
    int e = idx >> 5;
    int q = idx & 31;
    int s = ei[e];
    int d = ei[EE + e];
    float4 v = *((const float4*)&g_h[s * HH + q * 4]);
    float* p = &g_t[d * HH + q * 4];
    atomicAdd(p + 0, v.x);
    atomicAdd(p + 1, v.y);
    atomicAdd(p + 2, v.z);
    atomicAdd(p + 3, v.w);
}

// ---- 128x128 GEMM: C = ReLU( (optionally BN)( A @ W + b ) ) ----
// A: [NN,128] row-major (buffer srcid), W: [128,128] row-major, C: buffer dstid
__global__ __launch_bounds__(256) void k_gemm(
    int srcid, int dstid,
    const float* __restrict__ W, const float* __restrict__ bias,
    const float* __restrict__ gam, const float* __restrict__ bet,
    const float* __restrict__ mu, const float* __restrict__ var, int use_bn) {
    const float* A = buf(srcid);
    float* C = buf(dstid);

    __shared__ float As[128][36];  // pad 36 (16B-aligned rows, conflict-free)
    __shared__ float Ws[32][128];

    int tid = threadIdx.x;
    int tx = tid & 15;   // col group (8 cols each)
    int ty = tid >> 4;   // row group (8 rows each)
    int row0 = blockIdx.x * 128;

    float acc[8][8];
#pragma unroll
    for (int i = 0; i < 8; i++)
#pragma unroll
        for (int j = 0; j < 8; j++) acc[i][j] = 0.f;

    for (int kc = 0; kc < 4; kc++) {
        // load A tile 128x32
#pragma unroll
        for (int i = 0; i < 4; i++) {
            int r = (tid >> 3) + i * 32;
            int q = tid & 7;
            int row = row0 + r;
            float4 v = make_float4(0.f, 0.f, 0.f, 0.f);
            if (row < NN) v = *((const float4*)&A[row * 128 + kc * 32 + q * 4]);
            *((float4*)&As[r][q * 4]) = v;
        }
        // load W tile 32x128
#pragma unroll
        for (int i = 0; i < 4; i++) {
            int idx = tid + i * 256;
            int k = idx >> 5;
            int q = idx & 31;
            *((float4*)&Ws[k][q * 4]) = *((const float4*)&W[(kc * 32 + k) * 128 + q * 4]);
        }
        __syncthreads();

#pragma unroll
        for (int k = 0; k < 32; k++) {
            float a[8];
#pragma unroll
            for (int i = 0; i < 8; i++) a[i] = As[ty * 8 + i][k];
            float4 w0 = *((const float4*)&Ws[k][tx * 8]);
            float4 w1 = *((const float4*)&Ws[k][tx * 8 + 4]);
            float w[8] = {w0.x, w0.y, w0.z, w0.w, w1.x, w1.y, w1.z, w1.w};
#pragma unroll
            for (int i = 0; i < 8; i++)
#pragma unroll
                for (int j = 0; j < 8; j++)
                    acc[i][j] = fmaf(a[i], w[j], acc[i][j]);
        }
        __syncthreads();
    }

    // epilogue: bias (+ BN) + ReLU
    int colb = tx * 8;
    float bb[8], sc[8], sh[8];
#pragma unroll
    for (int j = 0; j < 8; j++) {
        bb[j] = bias[colb + j];
        if (use_bn) {
            float s = gam[colb + j] * rsqrtf(var[colb + j] + BN_EPS);
            sc[j] = s;
            sh[j] = bet[colb + j] - mu[colb + j] * s;
        }
    }
#pragma unroll
    for (int i = 0; i < 8; i++) {
        int row = row0 + ty * 8 + i;
        if (row >= NN) continue;
        float o[8];
#pragma unroll
        for (int j = 0; j < 8; j++) {
            float c = acc[i][j] + bb[j];
            if (use_bn) c = c * sc[j] + sh[j];
            o[j] = fmaxf(c, 0.f);
        }
        *((float4*)&C[row * 128 + colb]) = make_float4(o[0], o[1], o[2], o[3]);
        *((float4*)&C[row * 128 + colb + 4]) = make_float4(o[4], o[5], o[6], o[7]);
    }
}

// ---- pooling ----
__global__ void k_zero_pool() {
    int i = blockIdx.x * blockDim.x + threadIdx.x;
    if (i < GG * HH) g_pool[i] = 0.f;
}

__global__ void k_pool(const int* __restrict__ batch) {
    int idx = blockIdx.x * blockDim.x + threadIdx.x;
    if (idx >= NN * 32) return;
    int n = idx >> 5;
    int q = idx & 31;
    int b = batch[n];
    float4 v = *((const float4*)&g_h[n * 128 + q * 4]);
    float* p = &g_pool[b * 128 + q * 4];
    atomicAdd(p + 0, v.x);
    atomicAdd(p + 1, v.y);
    atomicAdd(p + 2, v.z);
    atomicAdd(p + 3, v.w);
}

__global__ void k_classify(const float* __restrict__ Wc, const float* __restrict__ bc,
                           float* __restrict__ out) {
    int g = blockIdx.x;
    int t = threadIdx.x;
    __shared__ float s[128];
    s[t] = g_pool[g * 128 + t] * Wc[t];
    __syncthreads();
#pragma unroll
    for (int st = 64; st > 0; st >>= 1) {
        if (t < st) s[t] += s[t + st];
        __syncthreads();
    }
    if (t == 0) out[g] = s[0] + bc[0];
}

extern "C" void kernel_launch(void* const* d_in, const int* in_sizes, int n_in,
                              void* d_out, int out_size) {
    const float* x       = (const float*)d_in[0];
    const int* ei        = (const int*)d_in[1];
    const int* batch     = (const int*)d_in[2];
    const float* W1_0 = (const float*)d_in[3];
    const float* b1_0 = (const float*)d_in[4];
    const float* g_0  = (const float*)d_in[5];
    const float* be_0 = (const float*)d_in[6];
    const float* m_0  = (const float*)d_in[7];
    const float* v_0  = (const float*)d_in[8];
    const float* W2_0 = (const float*)d_in[9];
    const float* b2_0 = (const float*)d_in[10];
    const float* W1s  = (const float*)d_in[11];
    const float* b1s  = (const float*)d_in[12];
    const float* gs   = (const float*)d_in[13];
    const float* bes  = (const float*)d_in[14];
    const float* ms   = (const float*)d_in[15];
    const float* vs   = (const float*)d_in[16];
    const float* W2s  = (const float*)d_in[17];
    const float* b2s  = (const float*)d_in[18];
    const float* Wc   = (const float*)d_in[19];
    const float* bc   = (const float*)d_in[20];
    float* out = (float*)d_out;

    const int T = 256;
    const int gemm_grid = (NN + 127) / 128;

    // ---- layer 0 (in=3) ----
    k_copy3<<<(NN * 3 + T - 1) / T, T>>>(x);
    k_scatter3<<<(EE + T - 1) / T, T>>>(x, ei);
    k_mlp0<<<(NN * HH + T - 1) / T, T>>>(W1_0, b1_0, g_0, be_0, m_0, v_0);
    // GEMM2: g_u -> g_h, ReLU only
    k_gemm<<<gemm_grid, 256>>>(1, 2, W2_0, b2_0, b2_0, b2_0, b2_0, b2_0, 0);

    // ---- layers 1..4 (in=128) ----
    for (int l = 0; l < 4; l++) {
        k_copyh<<<(NN * HH / 4 + T - 1) / T, T>>>();
        k_scatter<<<(EE * 32 + T - 1) / T, T>>>(ei);
        k_gemm<<<gemm_grid, 256>>>(0, 1, W1s + l * HH * HH, b1s + l * HH,
                                   gs + l * HH, bes + l * HH, ms + l * HH, vs + l * HH, 1);
        k_gemm<<<gemm_grid, 256>>>(1, 2, W2s + l * HH * HH, b2s + l * HH,
                                   b2s, b2s, b2s, b2s, 0);
    }

    // ---- pool + classify ----
    k_zero_pool<<<(GG * HH + T - 1) / T, T>>>();
    k_pool<<<(NN * 32 + T - 1) / T, T>>>(batch);
    k_classify<<<GG, 128>>>(Wc, bc, out);
}

// round 3
// speedup vs baseline: 2.1260x; 2.1260x over previous
#include <cuda_runtime.h>
#include <cstdint>

#define NN 100000
#define EE 600000
#define HH 128
#define GG 1000
#define BN_EPS 1e-5f

// ---- scratch (alloc-free: __device__ globals) ----
__device__ float g_t[NN * HH];     // x + agg (pre-MLP accumulator)
__device__ float g_u[NN * HH];     // after GEMM1+BN+ReLU
__device__ float g_h[NN * HH];     // layer output features
__device__ float g_t3[NN * 3];     // layer-0 pre-MLP (3 feats)
__device__ float g_pool[GG * HH];  // pooled per-graph

__device__ __forceinline__ float* buf(int id) {
    return id == 0 ? g_t : (id == 1 ? g_u : g_h);
}

__device__ __forceinline__ uint32_t f2tf32(float f) {
    uint32_t o;
    asm("cvt.rna.tf32.f32 %0, %1;" : "=r"(o) : "f"(f));
    return o;
}

__device__ __forceinline__ void red_add_v4(float* p, float4 v) {
    asm volatile("red.global.add.v4.f32 [%0], {%1,%2,%3,%4};"
                 :: "l"(p), "f"(v.x), "f"(v.y), "f"(v.z), "f"(v.w) : "memory");
}

// ---- layer 0: copy x into t3 ----
__global__ void k_copy3(const float* __restrict__ x) {
    int i = blockIdx.x * blockDim.x + threadIdx.x;
    if (i < NN * 3) g_t3[i] = x[i];
}

// ---- layer 0: scatter-add x[src] into t3[dst] (3 feats/edge) ----
__global__ void k_scatter3(const float* __restrict__ x, const int* __restrict__ ei) {
    int e = blockIdx.x * blockDim.x + threadIdx.x;
    if (e >= EE) return;
    int s = ei[e];
    int d = ei[EE + e];
#pragma unroll
    for (int f = 0; f < 3; f++) atomicAdd(&g_t3[d * 3 + f], x[s * 3 + f]);
}

// ---- layer 0: (N,3)@(3,128) + bias + BN + ReLU -> g_u ----
__global__ void k_mlp0(const float* __restrict__ W1, const float* __restrict__ b1,
                       const float* __restrict__ gam, const float* __restrict__ bet,
                       const float* __restrict__ mu, const float* __restrict__ var) {
    int idx = blockIdx.x * blockDim.x + threadIdx.x;
    if (idx >= NN * HH) return;
    int n = idx >> 7;
    int j = idx & 127;
    float h = g_t3[n * 3 + 0] * W1[j]
            + g_t3[n * 3 + 1] * W1[HH + j]
            + g_t3[n * 3 + 2] * W1[2 * HH + j]
            + b1[j];
    float sc = gam[j] * rsqrtf(var[j] + BN_EPS);
    h = (h - mu[j]) * sc + bet[j];
    g_u[idx] = fmaxf(h, 0.f);
}

// ---- edge scatter: g_t[dst] += g_h[src], one thread per (edge, float4) ----
__global__ void k_scatter(const int* __restrict__ ei) {
    int idx = blockIdx.x * blockDim.x + threadIdx.x;
    if (idx >= EE * 32) return;
    int e = idx >> 5;
    int q = idx & 31;
    int s = ei[e];
    int d = ei[EE + e];
    float4 v = *((const float4*)&g_h[s * HH + q * 4]);
    red_add_v4(&g_t[d * HH + q * 4], v);
}

// ---- tensor-core GEMM: C = ReLU( (BN)( A @ W + b ) ), A:[NN,128], W:[128,128]
// mma.sync.m16n8k8 tf32. 256 threads = 8 warps; warp tile 32x64 (2 m-tiles x 8 n-tiles).
__global__ __launch_bounds__(256) void k_gemm_tc(
    int srcid, int dstid,
    const float* __restrict__ W, const float* __restrict__ bias,
    const float* __restrict__ gam, const float* __restrict__ bet,
    const float* __restrict__ mu, const float* __restrict__ var,
    int use_bn, int dual) {
    const float* A = buf(srcid);
    float* C = buf(dstid);

    __shared__ float As[128][36];   // pad 36: banks 4*t2+t1 conflict-free
    __shared__ float Ws[32][136];   // pad 136: banks 8*t1+t2 conflict-free

    int tid = threadIdx.x;
    int warp = tid >> 5, lane = tid & 31;
    int wm = warp & 3;              // 4 warps over M (32 rows each)
    int wn = warp >> 2;             // 2 warps over N (64 cols each)
    int gq = lane >> 2;             // group id 0..7
    int tg = lane & 3;              // thread in group 0..3
    int row0 = blockIdx.x * 128;

    float c[2][8][4];
#pragma unroll
    for (int mt = 0; mt < 2; mt++)
#pragma unroll
        for (int nt = 0; nt < 8; nt++)
#pragma unroll
            for (int r = 0; r < 4; r++) c[mt][nt][r] = 0.f;

    for (int kc = 0; kc < 4; kc++) {
        // load A tile 128x32 (tf32-rounded)
#pragma unroll
        for (int i = 0; i < 4; i++) {
            int r = (tid >> 3) + i * 32;
            int q = tid & 7;
            int row = row0 + r;
            float4 v = make_float4(0.f, 0.f, 0.f, 0.f);
            if (row < NN) v = *((const float4*)&A[row * 128 + kc * 32 + q * 4]);
            As[r][q * 4 + 0] = __uint_as_float(f2tf32(v.x));
            As[r][q * 4 + 1] = __uint_as_float(f2tf32(v.y));
            As[r][q * 4 + 2] = __uint_as_float(f2tf32(v.z));
            As[r][q * 4 + 3] = __uint_as_float(f2tf32(v.w));
        }
        // load W tile 32x128 (tf32-rounded)
#pragma unroll
        for (int i = 0; i < 4; i++) {
            int idx = tid + i * 256;
            int k = idx >> 5;
            int q = idx & 31;
            float4 v = *((const float4*)&W[(kc * 32 + k) * 128 + q * 4]);
            Ws[k][q * 4 + 0] = __uint_as_float(f2tf32(v.x));
            Ws[k][q * 4 + 1] = __uint_as_float(f2tf32(v.y));
            Ws[k][q * 4 + 2] = __uint_as_float(f2tf32(v.z));
            Ws[k][q * 4 + 3] = __uint_as_float(f2tf32(v.w));
        }
        __syncthreads();

#pragma unroll
        for (int ks = 0; ks < 4; ks++) {
            int k0 = ks * 8;
            uint32_t a[2][4];
#pragma unroll
            for (int mt = 0; mt < 2; mt++) {
                int rb = wm * 32 + mt * 16;
                a[mt][0] = __float_as_uint(As[rb + gq][k0 + tg]);
                a[mt][1] = __float_as_uint(As[rb + gq + 8][k0 + tg]);
                a[mt][2] = __float_as_uint(As[rb + gq][k0 + tg + 4]);
                a[mt][3] = __float_as_uint(As[rb + gq + 8][k0 + tg + 4]);
            }
            uint32_t b[8][2];
#pragma unroll
            for (int nt = 0; nt < 8; nt++) {
                int col = wn * 64 + nt * 8 + gq;
                b[nt][0] = __float_as_uint(Ws[k0 + tg][col]);
                b[nt][1] = __float_as_uint(Ws[k0 + 4 + tg][col]);
            }
#pragma unroll
            for (int mt = 0; mt < 2; mt++)
#pragma unroll
                for (int nt = 0; nt < 8; nt++) {
                    asm volatile(
                        "mma.sync.aligned.m16n8k8.row.col.f32.tf32.tf32.f32 "
                        "{%0,%1,%2,%3}, {%4,%5,%6,%7}, {%8,%9}, {%0,%1,%2,%3};"
                        : "+f"(c[mt][nt][0]), "+f"(c[mt][nt][1]),
                          "+f"(c[mt][nt][2]), "+f"(c[mt][nt][3])
                        : "r"(a[mt][0]), "r"(a[mt][1]), "r"(a[mt][2]), "r"(a[mt][3]),
                          "r"(b[nt][0]), "r"(b[nt][1]));
                }
        }
        __syncthreads();
    }

    // epilogue: bias (+BN) + ReLU; c{0,1}: row gq, cols 2*tg,+1; c{2,3}: row gq+8
#pragma unroll
    for (int nt = 0; nt < 8; nt++) {
        int col = wn * 64 + nt * 8 + tg * 2;
        float sc0 = 1.f, sc1 = 1.f, sh0 = bias[col], sh1 = bias[col + 1];
        if (use_bn) {
            float s0 = gam[col] * rsqrtf(var[col] + BN_EPS);
            float s1 = gam[col + 1] * rsqrtf(var[col + 1] + BN_EPS);
            sh0 = (sh0 - mu[col]) * s0 + bet[col];
            sh1 = (sh1 - mu[col + 1]) * s1 + bet[col + 1];
            sc0 = s0; sc1 = s1;
        }
#pragma unroll
        for (int mt = 0; mt < 2; mt++) {
            int r0 = row0 + wm * 32 + mt * 16 + gq;
#pragma unroll
            for (int half = 0; half < 2; half++) {
                int row = r0 + half * 8;
                if (row >= NN) continue;
                float v0 = fmaxf(c[mt][nt][half * 2 + 0] * sc0 + sh0, 0.f);
                float v1 = fmaxf(c[mt][nt][half * 2 + 1] * sc1 + sh1, 0.f);
                float2 o = make_float2(v0, v1);
                *((float2*)&C[row * 128 + col]) = o;
                if (dual) *((float2*)&g_t[row * 128 + col]) = o;
            }
        }
    }
}

// ---- pooling ----
__global__ void k_zero_pool() {
    int i = blockIdx.x * blockDim.x + threadIdx.x;
    if (i < GG * HH) g_pool[i] = 0.f;
}

__global__ void k_pool(const int* __restrict__ batch) {
    int idx = blockIdx.x * blockDim.x + threadIdx.x;
    if (idx >= NN * 32) return;
    int n = idx >> 5;
    int q = idx & 31;
    int b = batch[n];
    float4 v = *((const float4*)&g_h[n * 128 + q * 4]);
    red_add_v4(&g_pool[b * 128 + q * 4], v);
}

__global__ void k_classify(const float* __restrict__ Wc, const float* __restrict__ bc,
                           float* __restrict__ out) {
    int g = blockIdx.x;
    int t = threadIdx.x;
    __shared__ float s[128];
    s[t] = g_pool[g * 128 + t] * Wc[t];
    __syncthreads();
#pragma unroll
    for (int st = 64; st > 0; st >>= 1) {
        if (t < st) s[t] += s[t + st];
        __syncthreads();
    }
    if (t == 0) out[g] = s[0] + bc[0];
}

extern "C" void kernel_launch(void* const* d_in, const int* in_sizes, int n_in,
                              void* d_out, int out_size) {
    const float* x       = (const float*)d_in[0];
    const int* ei        = (const int*)d_in[1];
    const int* batch     = (const int*)d_in[2];
    const float* W1_0 = (const float*)d_in[3];
    const float* b1_0 = (const float*)d_in[4];
    const float* g_0  = (const float*)d_in[5];
    const float* be_0 = (const float*)d_in[6];
    const float* m_0  = (const float*)d_in[7];
    const float* v_0  = (const float*)d_in[8];
    const float* W2_0 = (const float*)d_in[9];
    const float* b2_0 = (const float*)d_in[10];
    const float* W1s  = (const float*)d_in[11];
    const float* b1s  = (const float*)d_in[12];
    const float* gs   = (const float*)d_in[13];
    const float* bes  = (const float*)d_in[14];
    const float* ms   = (const float*)d_in[15];
    const float* vs   = (const float*)d_in[16];
    const float* W2s  = (const float*)d_in[17];
    const float* b2s  = (const float*)d_in[18];
    const float* Wc   = (const float*)d_in[19];
    const float* bc   = (const float*)d_in[20];
    float* out = (float*)d_out;

    const int T = 256;
    const int gemm_grid = (NN + 127) / 128;

    // ---- layer 0 (in=3) ----
    k_copy3<<<(NN * 3 + T - 1) / T, T>>>(x);
    k_scatter3<<<(EE + T - 1) / T, T>>>(x, ei);
    k_mlp0<<<(NN * HH + T - 1) / T, T>>>(W1_0, b1_0, g_0, be_0, m_0, v_0);
    // GEMM2: g_u -> g_h (+ dual-write g_t for next layer's scatter)
    k_gemm_tc<<<gemm_grid, 256>>>(1, 2, W2_0, b2_0, b2_0, b2_0, b2_0, b2_0, 0, 1);

    // ---- layers 1..4 (in=128) ----
    for (int l = 0; l < 4; l++) {
        k_scatter<<<(EE * 32 + T - 1) / T, T>>>(ei);
        k_gemm_tc<<<gemm_grid, 256>>>(0, 1, W1s + l * HH * HH, b1s + l * HH,
                                      gs + l * HH, bes + l * HH, ms + l * HH, vs + l * HH, 1, 0);
        k_gemm_tc<<<gemm_grid, 256>>>(1, 2, W2s + l * HH * HH, b2s + l * HH,
                                      b2s, b2s, b2s, b2s, 0, (l < 3) ? 1 : 0);
    }

    // ---- pool + classify ----
    k_zero_pool<<<(GG * HH + T - 1) / T, T>>>();
    k_pool<<<(NN * 32 + T - 1) / T, T>>>(batch);
    k_classify<<<GG, 128>>>(Wc, bc, out);
}

// round 5
// speedup vs baseline: 2.6576x; 1.2501x over previous
#include <cuda_runtime.h>
#include <cstdint>

#define NN 100000
#define EE 600000
#define HH 128
#define GG 1000
#define BN_EPS 1e-5f

// ---- scratch (alloc-free: __device__ globals) ----
__device__ float g_t[NN * HH];     // x + agg (pre-MLP accumulator)
__device__ float g_h[NN * HH];     // layer output features
__device__ float g_t3[NN * 3];     // layer-0 pre-MLP (3 feats)
__device__ float g_pool[GG * HH];  // pooled per-graph

// smem layout (floats)
#define US_STRIDE 132              // 132 % 32 == 4 -> bank = 4r+c (conflict-free quads)
#define AS_STRIDE 36
#define WS_STRIDE 136
#define US_OFF 0
#define AS_OFF (128 * US_STRIDE)
#define WS_OFF (AS_OFF + 128 * AS_STRIDE)
#define SMEM_FLOATS (WS_OFF + 32 * WS_STRIDE)
#define SMEM_BYTES (SMEM_FLOATS * 4)

__device__ __forceinline__ uint32_t f2tf32(float f) {
    uint32_t o;
    asm("cvt.rna.tf32.f32 %0, %1;" : "=r"(o) : "f"(f));
    return o;
}

__device__ __forceinline__ void red_add_v4(float* p, float4 v) {
    asm volatile("red.global.add.v4.f32 [%0], {%1,%2,%3,%4};"
                 :: "l"(p), "f"(v.x), "f"(v.y), "f"(v.z), "f"(v.w) : "memory");
}

// ---- layer 0: copy x into t3 ----
__global__ void k_copy3(const float* __restrict__ x) {
    int i = blockIdx.x * blockDim.x + threadIdx.x;
    if (i < NN * 3) g_t3[i] = x[i];
}

// ---- layer 0: scatter-add x[src] into t3[dst] (3 feats/edge) ----
__global__ void k_scatter3(const float* __restrict__ x, const int* __restrict__ ei) {
    int e = blockIdx.x * blockDim.x + threadIdx.x;
    if (e >= EE) return;
    int s = ei[e];
    int d = ei[EE + e];
#pragma unroll
    for (int f = 0; f < 3; f++) atomicAdd(&g_t3[d * 3 + f], x[s * 3 + f]);
}

// ---- edge scatter: g_t[dst] += g_h[src], one thread per (edge, float4) ----
__global__ void k_scatter(const int* __restrict__ ei) {
    int idx = blockIdx.x * blockDim.x + threadIdx.x;
    if (idx >= EE * 32) return;
    int e = idx >> 5;
    int q = idx & 31;
    int s = ei[e];
    int d = ei[EE + e];
    float4 v = *((const float4*)&g_h[s * HH + q * 4]);
    red_add_v4(&g_t[d * HH + q * 4], v);
}

// ---- fused per-layer MLP: h = ReLU(ReLU(BN(t@W1+b1)) @ W2 + b2) ----
// stage1 result kept in smem (tf32); stage2 mma reads it directly.
// layer0: stage1 is the tiny (N,3)@(3,128) MLP from g_t3.
__global__ __launch_bounds__(256, 2) void k_fused(
    int layer0,
    const float* __restrict__ W1, const float* __restrict__ b1,
    const float* __restrict__ gam, const float* __restrict__ bet,
    const float* __restrict__ mu, const float* __restrict__ var,
    const float* __restrict__ W2, const float* __restrict__ b2,
    int dual) {
    extern __shared__ float smem[];
    float* Us = smem + US_OFF;
    float* As = smem + AS_OFF;
    float* Ws = smem + WS_OFF;

    int tid = threadIdx.x;
    int warp = tid >> 5, lane = tid & 31;
    int wm = warp & 3;   // 4 warps over M (32 rows each)
    int wn = warp >> 2;  // 2 warps over N (64 cols each)
    int gq = lane >> 2;  // 0..7
    int tg = lane & 3;   // 0..3
    int row0 = blockIdx.x * 128;

    // ================= stage 1 =================
    if (layer0) {
        // W1 (3x128), BN scale/shift cached in smem (As region is free)
        float* W1s = As;         // 384 floats
        float* sc = As + 384;    // 128
        float* sh = As + 512;    // 128
        for (int i = tid; i < 384; i += 256) W1s[i] = W1[i];   // FIX: cover all 384
        if (tid < 128) {
            float s = gam[tid] * rsqrtf(var[tid] + BN_EPS);
            sc[tid] = s;
            sh[tid] = bet[tid] + (b1[tid] - mu[tid]) * s;
        }
        __syncthreads();
#pragma unroll 4
        for (int i = 0; i < 64; i++) {
            int idx = tid + i * 256;
            int r = idx >> 7, c = idx & 127;
            int row = row0 + r;
            float x0 = 0.f, x1 = 0.f, x2 = 0.f;
            if (row < NN) {
                x0 = g_t3[row * 3 + 0];
                x1 = g_t3[row * 3 + 1];
                x2 = g_t3[row * 3 + 2];
            }
            float u = x0 * W1s[c] + x1 * W1s[128 + c] + x2 * W1s[256 + c];
            u = fmaxf(u * sc[c] + sh[c], 0.f);
            Us[r * US_STRIDE + c] = __uint_as_float(f2tf32(u));
        }
        __syncthreads();
    } else {
        float c1[2][8][4];
#pragma unroll
        for (int mt = 0; mt < 2; mt++)
#pragma unroll
            for (int nt = 0; nt < 8; nt++)
#pragma unroll
                for (int r = 0; r < 4; r++) c1[mt][nt][r] = 0.f;

        for (int kc = 0; kc < 4; kc++) {
            // A chunk from g_t (tf32)
#pragma unroll
            for (int i = 0; i < 4; i++) {
                int r = (tid >> 3) + i * 32;
                int q = tid & 7;
                int row = row0 + r;
                float4 v = make_float4(0.f, 0.f, 0.f, 0.f);
                if (row < NN) v = *((const float4*)&g_t[row * 128 + kc * 32 + q * 4]);
                As[r * AS_STRIDE + q * 4 + 0] = __uint_as_float(f2tf32(v.x));
                As[r * AS_STRIDE + q * 4 + 1] = __uint_as_float(f2tf32(v.y));
                As[r * AS_STRIDE + q * 4 + 2] = __uint_as_float(f2tf32(v.z));
                As[r * AS_STRIDE + q * 4 + 3] = __uint_as_float(f2tf32(v.w));
            }
            // W1 chunk
#pragma unroll
            for (int i = 0; i < 4; i++) {
                int idx = tid + i * 256;
                int k = idx >> 5;
                int q = idx & 31;
                float4 v = *((const float4*)&W1[(kc * 32 + k) * 128 + q * 4]);
                Ws[k * WS_STRIDE + q * 4 + 0] = __uint_as_float(f2tf32(v.x));
                Ws[k * WS_STRIDE + q * 4 + 1] = __uint_as_float(f2tf32(v.y));
                Ws[k * WS_STRIDE + q * 4 + 2] = __uint_as_float(f2tf32(v.z));
                Ws[k * WS_STRIDE + q * 4 + 3] = __uint_as_float(f2tf32(v.w));
            }
            __syncthreads();
#pragma unroll
            for (int ks = 0; ks < 4; ks++) {
                int k0 = ks * 8;
                uint32_t a[2][4];
#pragma unroll
                for (int mt = 0; mt < 2; mt++) {
                    int rb = wm * 32 + mt * 16;
                    a[mt][0] = __float_as_uint(As[(rb + gq) * AS_STRIDE + k0 + tg]);
                    a[mt][1] = __float_as_uint(As[(rb + gq + 8) * AS_STRIDE + k0 + tg]);
                    a[mt][2] = __float_as_uint(As[(rb + gq) * AS_STRIDE + k0 + tg + 4]);
                    a[mt][3] = __float_as_uint(As[(rb + gq + 8) * AS_STRIDE + k0 + tg + 4]);
                }
                uint32_t b[8][2];
#pragma unroll
                for (int nt = 0; nt < 8; nt++) {
                    int col = wn * 64 + nt * 8 + gq;
                    b[nt][0] = __float_as_uint(Ws[(k0 + tg) * WS_STRIDE + col]);
                    b[nt][1] = __float_as_uint(Ws[(k0 + 4 + tg) * WS_STRIDE + col]);
                }
#pragma unroll
                for (int mt = 0; mt < 2; mt++)
#pragma unroll
                    for (int nt = 0; nt < 8; nt++) {
                        asm volatile(
                            "mma.sync.aligned.m16n8k8.row.col.f32.tf32.tf32.f32 "
                            "{%0,%1,%2,%3}, {%4,%5,%6,%7}, {%8,%9}, {%0,%1,%2,%3};"
                            : "+f"(c1[mt][nt][0]), "+f"(c1[mt][nt][1]),
                              "+f"(c1[mt][nt][2]), "+f"(c1[mt][nt][3])
                            : "r"(a[mt][0]), "r"(a[mt][1]), "r"(a[mt][2]), "r"(a[mt][3]),
                              "r"(b[nt][0]), "r"(b[nt][1]));
                    }
            }
            __syncthreads();
        }

        // BN + ReLU -> Us (tf32)
#pragma unroll
        for (int nt = 0; nt < 8; nt++) {
            int col = wn * 64 + nt * 8 + tg * 2;
            float s0 = gam[col] * rsqrtf(var[col] + BN_EPS);
            float s1 = gam[col + 1] * rsqrtf(var[col + 1] + BN_EPS);
            float sh0 = bet[col] + (b1[col] - mu[col]) * s0;
            float sh1 = bet[col + 1] + (b1[col + 1] - mu[col + 1]) * s1;
#pragma unroll
            for (int mt = 0; mt < 2; mt++) {
                int rb = wm * 32 + mt * 16 + gq;
#pragma unroll
                for (int half = 0; half < 2; half++) {
                    int r = rb + half * 8;
                    float v0 = fmaxf(c1[mt][nt][half * 2 + 0] * s0 + sh0, 0.f);
                    float v1 = fmaxf(c1[mt][nt][half * 2 + 1] * s1 + sh1, 0.f);
                    Us[r * US_STRIDE + col] = __uint_as_float(f2tf32(v0));
                    Us[r * US_STRIDE + col + 1] = __uint_as_float(f2tf32(v1));
                }
            }
        }
        __syncthreads();
    }

    // ================= stage 2: h = ReLU(Us @ W2 + b2) =================
    float c2[2][8][4];
#pragma unroll
    for (int mt = 0; mt < 2; mt++)
#pragma unroll
        for (int nt = 0; nt < 8; nt++)
#pragma unroll
            for (int r = 0; r < 4; r++) c2[mt][nt][r] = 0.f;

    for (int kc = 0; kc < 4; kc++) {
        // W2 chunk
#pragma unroll
        for (int i = 0; i < 4; i++) {
            int idx = tid + i * 256;
            int k = idx >> 5;
            int q = idx & 31;
            float4 v = *((const float4*)&W2[(kc * 32 + k) * 128 + q * 4]);
            Ws[k * WS_STRIDE + q * 4 + 0] = __uint_as_float(f2tf32(v.x));
            Ws[k * WS_STRIDE + q * 4 + 1] = __uint_as_float(f2tf32(v.y));
            Ws[k * WS_STRIDE + q * 4 + 2] = __uint_as_float(f2tf32(v.z));
            Ws[k * WS_STRIDE + q * 4 + 3] = __uint_as_float(f2tf32(v.w));
        }
        __syncthreads();
#pragma unroll
        for (int ks = 0; ks < 4; ks++) {
            int k0 = ks * 8;
            int kcol = kc * 32 + k0;
            uint32_t a[2][4];
#pragma unroll
            for (int mt = 0; mt < 2; mt++) {
                int rb = wm * 32 + mt * 16;
                a[mt][0] = __float_as_uint(Us[(rb + gq) * US_STRIDE + kcol + tg]);
                a[mt][1] = __float_as_uint(Us[(rb + gq + 8) * US_STRIDE + kcol + tg]);
                a[mt][2] = __float_as_uint(Us[(rb + gq) * US_STRIDE + kcol + tg + 4]);
                a[mt][3] = __float_as_uint(Us[(rb + gq + 8) * US_STRIDE + kcol + tg + 4]);
            }
            uint32_t b[8][2];
#pragma unroll
            for (int nt = 0; nt < 8; nt++) {
                int col = wn * 64 + nt * 8 + gq;
                b[nt][0] = __float_as_uint(Ws[(k0 + tg) * WS_STRIDE + col]);
                b[nt][1] = __float_as_uint(Ws[(k0 + 4 + tg) * WS_STRIDE + col]);
            }
#pragma unroll
            for (int mt = 0; mt < 2; mt++)
#pragma unroll
                for (int nt = 0; nt < 8; nt++) {
                    asm volatile(
                        "mma.sync.aligned.m16n8k8.row.col.f32.tf32.tf32.f32 "
                        "{%0,%1,%2,%3}, {%4,%5,%6,%7}, {%8,%9}, {%0,%1,%2,%3};"
                        : "+f"(c2[mt][nt][0]), "+f"(c2[mt][nt][1]),
                          "+f"(c2[mt][nt][2]), "+f"(c2[mt][nt][3])
                        : "r"(a[mt][0]), "r"(a[mt][1]), "r"(a[mt][2]), "r"(a[mt][3]),
                          "r"(b[nt][0]), "r"(b[nt][1]));
                }
        }
        __syncthreads();
    }

    // epilogue: bias + ReLU -> g_h (+ g_t if dual)
#pragma unroll
    for (int nt = 0; nt < 8; nt++) {
        int col = wn * 64 + nt * 8 + tg * 2;
        float sh0 = b2[col];
        float sh1 = b2[col + 1];
#pragma unroll
        for (int mt = 0; mt < 2; mt++) {
            int r0 = row0 + wm * 32 + mt * 16 + gq;
#pragma unroll
            for (int half = 0; half < 2; half++) {
                int row = r0 + half * 8;
                if (row >= NN) continue;
                float v0 = fmaxf(c2[mt][nt][half * 2 + 0] + sh0, 0.f);
                float v1 = fmaxf(c2[mt][nt][half * 2 + 1] + sh1, 0.f);
                float2 o = make_float2(v0, v1);
                *((float2*)&g_h[row * 128 + col]) = o;
                if (dual) *((float2*)&g_t[row * 128 + col]) = o;
            }
        }
    }
}

// ---- pooling ----
__global__ void k_zero_pool() {
    int i = blockIdx.x * blockDim.x + threadIdx.x;
    if (i < GG * HH) g_pool[i] = 0.f;
}

__global__ void k_pool(const int* __restrict__ batch) {
    int idx = blockIdx.x * blockDim.x + threadIdx.x;
    if (idx >= NN * 32) return;
    int n = idx >> 5;
    int q = idx & 31;
    int b = batch[n];
    float4 v = *((const float4*)&g_h[n * 128 + q * 4]);
    red_add_v4(&g_pool[b * 128 + q * 4], v);
}

__global__ void k_classify(const float* __restrict__ Wc, const float* __restrict__ bc,
                           float* __restrict__ out) {
    int g = blockIdx.x;
    int t = threadIdx.x;
    __shared__ float s[128];
    s[t] = g_pool[g * 128 + t] * Wc[t];
    __syncthreads();
#pragma unroll
    for (int st = 64; st > 0; st >>= 1) {
        if (t < st) s[t] += s[t + st];
        __syncthreads();
    }
    if (t == 0) out[g] = s[0] + bc[0];
}

extern "C" void kernel_launch(void* const* d_in, const int* in_sizes, int n_in,
                              void* d_out, int out_size) {
    const float* x    = (const float*)d_in[0];
    const int* ei     = (const int*)d_in[1];
    const int* batch  = (const int*)d_in[2];
    const float* W1_0 = (const float*)d_in[3];
    const float* b1_0 = (const float*)d_in[4];
    const float* g_0  = (const float*)d_in[5];
    const float* be_0 = (const float*)d_in[6];
    const float* m_0  = (const float*)d_in[7];
    const float* v_0  = (const float*)d_in[8];
    const float* W2_0 = (const float*)d_in[9];
    const float* b2_0 = (const float*)d_in[10];
    const float* W1s  = (const float*)d_in[11];
    const float* b1s  = (const float*)d_in[12];
    const float* gs   = (const float*)d_in[13];
    const float* bes  = (const float*)d_in[14];
    const float* ms   = (const float*)d_in[15];
    const float* vs   = (const float*)d_in[16];
    const float* W2s  = (const float*)d_in[17];
    const float* b2s  = (const float*)d_in[18];
    const float* Wc   = (const float*)d_in[19];
    const float* bc   = (const float*)d_in[20];
    float* out = (float*)d_out;

    cudaFuncSetAttribute(k_fused, cudaFuncAttributeMaxDynamicSharedMemorySize, SMEM_BYTES);

    const int T = 256;
    const int gemm_grid = (NN + 127) / 128;

    // ---- layer 0 (in=3): fused tiny-MLP + GEMM2, dual-write g_t ----
    k_copy3<<<(NN * 3 + T - 1) / T, T>>>(x);
    k_scatter3<<<(EE + T - 1) / T, T>>>(x, ei);
    k_fused<<<gemm_grid, 256, SMEM_BYTES>>>(1, W1_0, b1_0, g_0, be_0, m_0, v_0,
                                            W2_0, b2_0, 1);

    // ---- layers 1..4 (in=128) ----
    for (int l = 0; l < 4; l++) {
        k_scatter<<<(EE * 32 + T - 1) / T, T>>>(ei);
        k_fused<<<gemm_grid, 256, SMEM_BYTES>>>(0,
            W1s + l * HH * HH, b1s + l * HH,
            gs + l * HH, bes + l * HH, ms + l * HH, vs + l * HH,
            W2s + l * HH * HH, b2s + l * HH, (l < 3) ? 1 : 0);
    }

    // ---- pool + classify ----
    k_zero_pool<<<(GG * HH + T - 1) / T, T>>>();
    k_pool<<<(NN * 32 + T - 1) / T, T>>>(batch);
    k_classify<<<GG, 128>>>(Wc, bc, out);
}

// round 6
// speedup vs baseline: 3.6701x; 1.3810x over previous
#include <cuda_runtime.h>
#include <cstdint>

#define NN 100000
#define EE 600000
#define HH 128
#define GG 1000
#define BN_EPS 1e-5f
#define NB_SCAN 98   // ceil(NN/1024)

// ---- scratch (alloc-free: __device__ globals) ----
__device__ float g_t[NN * HH];     // h + agg (pre-MLP input)
__device__ float g_h[NN * HH];     // layer output features
__device__ float g_t3[NN * 3];     // layer-0 pre-MLP (3 feats)
__device__ float g_pool[GG * HH];  // pooled per-graph
// CSR scratch
__device__ int g_deg[NN];
__device__ int g_rowptr[NN + 1];
__device__ int g_cursor[NN];
__device__ int g_bsum[128];
__device__ int g_csr[EE];

// smem layout (floats)
#define US_STRIDE 132
#define AS_STRIDE 36
#define WS_STRIDE 136
#define US_OFF 0
#define AS_OFF (128 * US_STRIDE)
#define WS_OFF (AS_OFF + 128 * AS_STRIDE)
#define SMEM_FLOATS (WS_OFF + 32 * WS_STRIDE)
#define SMEM_BYTES (SMEM_FLOATS * 4)

__device__ __forceinline__ uint32_t f2tf32(float f) {
    uint32_t o;
    asm("cvt.rna.tf32.f32 %0, %1;" : "=r"(o) : "f"(f));
    return o;
}

__device__ __forceinline__ void red_add_v4(float* p, float4 v) {
    asm volatile("red.global.add.v4.f32 [%0], {%1,%2,%3,%4};"
                 :: "l"(p), "f"(v.x), "f"(v.y), "f"(v.z), "f"(v.w) : "memory");
}

// ================= CSR build =================
__global__ void k_zero_deg() {
    int i = blockIdx.x * blockDim.x + threadIdx.x;
    if (i < NN) g_deg[i] = 0;
}

__global__ void k_hist(const int* __restrict__ ei) {
    int e = blockIdx.x * blockDim.x + threadIdx.x;
    if (e < EE) atomicAdd(&g_deg[ei[EE + e]], 1);
}

// block-wise exclusive scan of g_deg into g_rowptr; block sums -> g_bsum
__global__ __launch_bounds__(1024) void k_scan1() {
    __shared__ int s[1024];
    int tid = threadIdx.x;
    int i = blockIdx.x * 1024 + tid;
    int v = (i < NN) ? g_deg[i] : 0;
    s[tid] = v;
    __syncthreads();
#pragma unroll
    for (int off = 1; off < 1024; off <<= 1) {
        int t = (tid >= off) ? s[tid - off] : 0;
        __syncthreads();
        s[tid] += t;
        __syncthreads();
    }
    if (i < NN) g_rowptr[i] = s[tid] - v;  // exclusive
    if (tid == 1023) g_bsum[blockIdx.x] = s[1023];
}

// scan the (<=128) block sums, exclusive, in place
__global__ void k_scan2() {
    __shared__ int s[128];
    int tid = threadIdx.x;
    int v = (tid < NB_SCAN) ? g_bsum[tid] : 0;
    s[tid] = v;
    __syncthreads();
#pragma unroll
    for (int off = 1; off < 128; off <<= 1) {
        int t = (tid >= off) ? s[tid - off] : 0;
        __syncthreads();
        s[tid] += t;
        __syncthreads();
    }
    if (tid < NB_SCAN) g_bsum[tid] = s[tid] - v;  // exclusive
}

// add block offsets; init cursor; set rowptr[NN]
__global__ void k_scan3() {
    int i = blockIdx.x * blockDim.x + threadIdx.x;
    if (i < NN) {
        int r = g_rowptr[i] + g_bsum[i >> 10];
        g_rowptr[i] = r;
        g_cursor[i] = r;
    }
    if (i == 0) g_rowptr[NN] = EE;
}

__global__ void k_reorder(const int* __restrict__ ei) {
    int e = blockIdx.x * blockDim.x + threadIdx.x;
    if (e >= EE) return;
    int s = ei[e];
    int d = ei[EE + e];
    int pos = atomicAdd(&g_cursor[d], 1);
    g_csr[pos] = s;
}

// ================= gathers =================
// layer 0: t3[n] = x[n] + sum_{s in N(n)} x[s]  (3 feats)
__global__ void k_gather3(const float* __restrict__ x) {
    int n = blockIdx.x * blockDim.x + threadIdx.x;
    if (n >= NN) return;
    int beg = g_rowptr[n], end = g_rowptr[n + 1];
    float a0 = x[n * 3 + 0], a1 = x[n * 3 + 1], a2 = x[n * 3 + 2];
    for (int p = beg; p < end; p++) {
        int s = g_csr[p];
        a0 += x[s * 3 + 0];
        a1 += x[s * 3 + 1];
        a2 += x[s * 3 + 2];
    }
    g_t3[n * 3 + 0] = a0;
    g_t3[n * 3 + 1] = a1;
    g_t3[n * 3 + 2] = a2;
}

// layers 1..4: g_t[n] = g_h[n] + sum_{s in N(n)} g_h[s]; warp per node
__global__ __launch_bounds__(256) void k_gather() {
    int n = blockIdx.x * 8 + (threadIdx.x >> 5);
    if (n >= NN) return;
    int lane = threadIdx.x & 31;
    int beg = g_rowptr[n], end = g_rowptr[n + 1];
    float4 acc = *((const float4*)&g_h[n * HH + lane * 4]);
    int p = beg;
    // 2-deep manual pipeline to overlap the dependent L2 loads
    for (; p + 1 < end; p += 2) {
        int s0 = g_csr[p], s1 = g_csr[p + 1];
        float4 v0 = *((const float4*)&g_h[s0 * HH + lane * 4]);
        float4 v1 = *((const float4*)&g_h[s1 * HH + lane * 4]);
        acc.x += v0.x + v1.x;
        acc.y += v0.y + v1.y;
        acc.z += v0.z + v1.z;
        acc.w += v0.w + v1.w;
    }
    if (p < end) {
        int s0 = g_csr[p];
        float4 v0 = *((const float4*)&g_h[s0 * HH + lane * 4]);
        acc.x += v0.x;
        acc.y += v0.y;
        acc.z += v0.z;
        acc.w += v0.w;
    }
    *((float4*)&g_t[n * HH + lane * 4]) = acc;
}

// ================= fused per-layer MLP =================
// h = ReLU(ReLU(BN(t@W1+b1)) @ W2 + b2); stage1 result in smem (tf32)
__global__ __launch_bounds__(256, 2) void k_fused(
    int layer0,
    const float* __restrict__ W1, const float* __restrict__ b1,
    const float* __restrict__ gam, const float* __restrict__ bet,
    const float* __restrict__ mu, const float* __restrict__ var,
    const float* __restrict__ W2, const float* __restrict__ b2) {
    extern __shared__ float smem[];
    float* Us = smem + US_OFF;
    float* As = smem + AS_OFF;
    float* Ws = smem + WS_OFF;

    int tid = threadIdx.x;
    int warp = tid >> 5, lane = tid & 31;
    int wm = warp & 3;
    int wn = warp >> 2;
    int gq = lane >> 2;
    int tg = lane & 3;
    int row0 = blockIdx.x * 128;

    // ---- stage 1 ----
    if (layer0) {
        float* W1s = As;
        float* sc = As + 384;
        float* sh = As + 512;
        for (int i = tid; i < 384; i += 256) W1s[i] = W1[i];
        if (tid < 128) {
            float s = gam[tid] * rsqrtf(var[tid] + BN_EPS);
            sc[tid] = s;
            sh[tid] = bet[tid] + (b1[tid] - mu[tid]) * s;
        }
        __syncthreads();
#pragma unroll 4
        for (int i = 0; i < 64; i++) {
            int idx = tid + i * 256;
            int r = idx >> 7, c = idx & 127;
            int row = row0 + r;
            float x0 = 0.f, x1 = 0.f, x2 = 0.f;
            if (row < NN) {
                x0 = g_t3[row * 3 + 0];
                x1 = g_t3[row * 3 + 1];
                x2 = g_t3[row * 3 + 2];
            }
            float u = x0 * W1s[c] + x1 * W1s[128 + c] + x2 * W1s[256 + c];
            u = fmaxf(u * sc[c] + sh[c], 0.f);
            Us[r * US_STRIDE + c] = __uint_as_float(f2tf32(u));
        }
        __syncthreads();
    } else {
        float c1[2][8][4];
#pragma unroll
        for (int mt = 0; mt < 2; mt++)
#pragma unroll
            for (int nt = 0; nt < 8; nt++)
#pragma unroll
                for (int r = 0; r < 4; r++) c1[mt][nt][r] = 0.f;

        for (int kc = 0; kc < 4; kc++) {
#pragma unroll
            for (int i = 0; i < 4; i++) {
                int r = (tid >> 3) + i * 32;
                int q = tid & 7;
                int row = row0 + r;
                float4 v = make_float4(0.f, 0.f, 0.f, 0.f);
                if (row < NN) v = *((const float4*)&g_t[row * 128 + kc * 32 + q * 4]);
                As[r * AS_STRIDE + q * 4 + 0] = __uint_as_float(f2tf32(v.x));
                As[r * AS_STRIDE + q * 4 + 1] = __uint_as_float(f2tf32(v.y));
                As[r * AS_STRIDE + q * 4 + 2] = __uint_as_float(f2tf32(v.z));
                As[r * AS_STRIDE + q * 4 + 3] = __uint_as_float(f2tf32(v.w));
            }
#pragma unroll
            for (int i = 0; i < 4; i++) {
                int idx = tid + i * 256;
                int k = idx >> 5;
                int q = idx & 31;
                float4 v = *((const float4*)&W1[(kc * 32 + k) * 128 + q * 4]);
                Ws[k * WS_STRIDE + q * 4 + 0] = __uint_as_float(f2tf32(v.x));
                Ws[k * WS_STRIDE + q * 4 + 1] = __uint_as_float(f2tf32(v.y));
                Ws[k * WS_STRIDE + q * 4 + 2] = __uint_as_float(f2tf32(v.z));
                Ws[k * WS_STRIDE + q * 4 + 3] = __uint_as_float(f2tf32(v.w));
            }
            __syncthreads();
#pragma unroll
            for (int ks = 0; ks < 4; ks++) {
                int k0 = ks * 8;
                uint32_t a[2][4];
#pragma unroll
                for (int mt = 0; mt < 2; mt++) {
                    int rb = wm * 32 + mt * 16;
                    a[mt][0] = __float_as_uint(As[(rb + gq) * AS_STRIDE + k0 + tg]);
                    a[mt][1] = __float_as_uint(As[(rb + gq + 8) * AS_STRIDE + k0 + tg]);
                    a[mt][2] = __float_as_uint(As[(rb + gq) * AS_STRIDE + k0 + tg + 4]);
                    a[mt][3] = __float_as_uint(As[(rb + gq + 8) * AS_STRIDE + k0 + tg + 4]);
                }
                uint32_t b[8][2];
#pragma unroll
                for (int nt = 0; nt < 8; nt++) {
                    int col = wn * 64 + nt * 8 + gq;
                    b[nt][0] = __float_as_uint(Ws[(k0 + tg) * WS_STRIDE + col]);
                    b[nt][1] = __float_as_uint(Ws[(k0 + 4 + tg) * WS_STRIDE + col]);
                }
#pragma unroll
                for (int mt = 0; mt < 2; mt++)
#pragma unroll
                    for (int nt = 0; nt < 8; nt++) {
                        asm volatile(
                            "mma.sync.aligned.m16n8k8.row.col.f32.tf32.tf32.f32 "
                            "{%0,%1,%2,%3}, {%4,%5,%6,%7}, {%8,%9}, {%0,%1,%2,%3};"
                            : "+f"(c1[mt][nt][0]), "+f"(c1[mt][nt][1]),
                              "+f"(c1[mt][nt][2]), "+f"(c1[mt][nt][3])
                            : "r"(a[mt][0]), "r"(a[mt][1]), "r"(a[mt][2]), "r"(a[mt][3]),
                              "r"(b[nt][0]), "r"(b[nt][1]));
                    }
            }
            __syncthreads();
        }

#pragma unroll
        for (int nt = 0; nt < 8; nt++) {
            int col = wn * 64 + nt * 8 + tg * 2;
            float s0 = gam[col] * rsqrtf(var[col] + BN_EPS);
            float s1 = gam[col + 1] * rsqrtf(var[col + 1] + BN_EPS);
            float sh0 = bet[col] + (b1[col] - mu[col]) * s0;
            float sh1 = bet[col + 1] + (b1[col + 1] - mu[col + 1]) * s1;
#pragma unroll
            for (int mt = 0; mt < 2; mt++) {
                int rb = wm * 32 + mt * 16 + gq;
#pragma unroll
                for (int half = 0; half < 2; half++) {
                    int r = rb + half * 8;
                    float v0 = fmaxf(c1[mt][nt][half * 2 + 0] * s0 + sh0, 0.f);
                    float v1 = fmaxf(c1[mt][nt][half * 2 + 1] * s1 + sh1, 0.f);
                    Us[r * US_STRIDE + col] = __uint_as_float(f2tf32(v0));
                    Us[r * US_STRIDE + col + 1] = __uint_as_float(f2tf32(v1));
                }
            }
        }
        __syncthreads();
    }

    // ---- stage 2: h = ReLU(Us @ W2 + b2) ----
    float c2[2][8][4];
#pragma unroll
    for (int mt = 0; mt < 2; mt++)
#pragma unroll
        for (int nt = 0; nt < 8; nt++)
#pragma unroll
            for (int r = 0; r < 4; r++) c2[mt][nt][r] = 0.f;

    for (int kc = 0; kc < 4; kc++) {
#pragma unroll
        for (int i = 0; i < 4; i++) {
            int idx = tid + i * 256;
            int k = idx >> 5;
            int q = idx & 31;
            float4 v = *((const float4*)&W2[(kc * 32 + k) * 128 + q * 4]);
            Ws[k * WS_STRIDE + q * 4 + 0] = __uint_as_float(f2tf32(v.x));
            Ws[k * WS_STRIDE + q * 4 + 1] = __uint_as_float(f2tf32(v.y));
            Ws[k * WS_STRIDE + q * 4 + 2] = __uint_as_float(f2tf32(v.z));
            Ws[k * WS_STRIDE + q * 4 + 3] = __uint_as_float(f2tf32(v.w));
        }
        __syncthreads();
#pragma unroll
        for (int ks = 0; ks < 4; ks++) {
            int k0 = ks * 8;
            int kcol = kc * 32 + k0;
            uint32_t a[2][4];
#pragma unroll
            for (int mt = 0; mt < 2; mt++) {
                int rb = wm * 32 + mt * 16;
                a[mt][0] = __float_as_uint(Us[(rb + gq) * US_STRIDE + kcol + tg]);
                a[mt][1] = __float_as_uint(Us[(rb + gq + 8) * US_STRIDE + kcol + tg]);
                a[mt][2] = __float_as_uint(Us[(rb + gq) * US_STRIDE + kcol + tg + 4]);
                a[mt][3] = __float_as_uint(Us[(rb + gq + 8) * US_STRIDE + kcol + tg + 4]);
            }
            uint32_t b[8][2];
#pragma unroll
            for (int nt = 0; nt < 8; nt++) {
                int col = wn * 64 + nt * 8 + gq;
                b[nt][0] = __float_as_uint(Ws[(k0 + tg) * WS_STRIDE + col]);
                b[nt][1] = __float_as_uint(Ws[(k0 + 4 + tg) * WS_STRIDE + col]);
            }
#pragma unroll
            for (int mt = 0; mt < 2; mt++)
#pragma unroll
                for (int nt = 0; nt < 8; nt++) {
                    asm volatile(
                        "mma.sync.aligned.m16n8k8.row.col.f32.tf32.tf32.f32 "
                        "{%0,%1,%2,%3}, {%4,%5,%6,%7}, {%8,%9}, {%0,%1,%2,%3};"
                        : "+f"(c2[mt][nt][0]), "+f"(c2[mt][nt][1]),
                          "+f"(c2[mt][nt][2]), "+f"(c2[mt][nt][3])
                        : "r"(a[mt][0]), "r"(a[mt][1]), "r"(a[mt][2]), "r"(a[mt][3]),
                          "r"(b[nt][0]), "r"(b[nt][1]));
                }
        }
        __syncthreads();
    }

#pragma unroll
    for (int nt = 0; nt < 8; nt++) {
        int col = wn * 64 + nt * 8 + tg * 2;
        float sh0 = b2[col];
        float sh1 = b2[col + 1];
#pragma unroll
        for (int mt = 0; mt < 2; mt++) {
            int r0 = row0 + wm * 32 + mt * 16 + gq;
#pragma unroll
            for (int half = 0; half < 2; half++) {
                int row = r0 + half * 8;
                if (row >= NN) continue;
                float v0 = fmaxf(c2[mt][nt][half * 2 + 0] + sh0, 0.f);
                float v1 = fmaxf(c2[mt][nt][half * 2 + 1] + sh1, 0.f);
                *((float2*)&g_h[row * 128 + col]) = make_float2(v0, v1);
            }
        }
    }
}

// ================= pooling =================
__global__ void k_zero_pool() {
    int i = blockIdx.x * blockDim.x + threadIdx.x;
    if (i < GG * HH) g_pool[i] = 0.f;
}

__global__ void k_pool(const int* __restrict__ batch) {
    int idx = blockIdx.x * blockDim.x + threadIdx.x;
    if (idx >= NN * 32) return;
    int n = idx >> 5;
    int q = idx & 31;
    int b = batch[n];
    float4 v = *((const float4*)&g_h[n * 128 + q * 4]);
    red_add_v4(&g_pool[b * 128 + q * 4], v);
}

__global__ void k_classify(const float* __restrict__ Wc, const float* __restrict__ bc,
                           float* __restrict__ out) {
    int g = blockIdx.x;
    int t = threadIdx.x;
    __shared__ float s[128];
    s[t] = g_pool[g * 128 + t] * Wc[t];
    __syncthreads();
#pragma unroll
    for (int st = 64; st > 0; st >>= 1) {
        if (t < st) s[t] += s[t + st];
        __syncthreads();
    }
    if (t == 0) out[g] = s[0] + bc[0];
}

extern "C" void kernel_launch(void* const* d_in, const int* in_sizes, int n_in,
                              void* d_out, int out_size) {
    const float* x    = (const float*)d_in[0];
    const int* ei     = (const int*)d_in[1];
    const int* batch  = (const int*)d_in[2];
    const float* W1_0 = (const float*)d_in[3];
    const float* b1_0 = (const float*)d_in[4];
    const float* g_0  = (const float*)d_in[5];
    const float* be_0 = (const float*)d_in[6];
    const float* m_0  = (const float*)d_in[7];
    const float* v_0  = (const float*)d_in[8];
    const float* W2_0 = (const float*)d_in[9];
    const float* b2_0 = (const float*)d_in[10];
    const float* W1s  = (const float*)d_in[11];
    const float* b1s  = (const float*)d_in[12];
    const float* gs   = (const float*)d_in[13];
    const float* bes  = (const float*)d_in[14];
    const float* ms   = (const float*)d_in[15];
    const float* vs   = (const float*)d_in[16];
    const float* W2s  = (const float*)d_in[17];
    const float* b2s  = (const float*)d_in[18];
    const float* Wc   = (const float*)d_in[19];
    const float* bc   = (const float*)d_in[20];
    float* out = (float*)d_out;

    cudaFuncSetAttribute(k_fused, cudaFuncAttributeMaxDynamicSharedMemorySize, SMEM_BYTES);

    const int T = 256;
    const int gemm_grid = (NN + 127) / 128;

    // ---- CSR build (dst-sorted adjacency) ----
    k_zero_deg<<<(NN + T - 1) / T, T>>>();
    k_hist<<<(EE + T - 1) / T, T>>>(ei);
    k_scan1<<<NB_SCAN, 1024>>>();
    k_scan2<<<1, 128>>>();
    k_scan3<<<(NN + T - 1) / T, T>>>();
    k_reorder<<<(EE + T - 1) / T, T>>>(ei);

    // ---- layer 0 (in=3) ----
    k_gather3<<<(NN + T - 1) / T, T>>>(x);
    k_fused<<<gemm_grid, 256, SMEM_BYTES>>>(1, W1_0, b1_0, g_0, be_0, m_0, v_0,
                                            W2_0, b2_0);

    // ---- layers 1..4 (in=128) ----
    for (int l = 0; l < 4; l++) {
        k_gather<<<(NN + 7) / 8, 256>>>();
        k_fused<<<gemm_grid, 256, SMEM_BYTES>>>(0,
            W1s + l * HH * HH, b1s + l * HH,
            gs + l * HH, bes + l * HH, ms + l * HH, vs + l * HH,
            W2s + l * HH * HH, b2s + l * HH);
    }

    // ---- pool + classify ----
    k_zero_pool<<<(GG * HH + T - 1) / T, T>>>();
    k_pool<<<(NN * 32 + T - 1) / T, T>>>(batch);
    k_classify<<<GG, 128>>>(Wc, bc, out);
}